// round 16
// baseline (speedup 1.0000x reference)
#include <cuda_runtime.h>

#define NPLANES 32
#define HW 65536
#define PR 32                         // vertical pad rows (>= max W)
#define PPL ((256 + 2 * PR) * 256)    // padded plane size in floats
#define SROW 368                      // skewed smem row stride (floats)

// A: y-padded H-dilate result (pads -1e4).  C: y-padded H-erode result (pads +1e4).
static __device__ float g_bufA[4 * NPLANES * PPL];
static __device__ float g_bufC[4 * NPLANES * PPL];

// ---------------------------------------------------------------------------
// hsweep: source-centric horizontal weighted opt over a skewed smem row.
// base = s + row*SROW + x0 + (x0>>3), x0 multiple of 8 (so skew decomposes:
// ind(x0+u) = ind(x0) + u + (u>>3), all compile-time per unrolled u).
// Each staged value read once; feeds up to 8 accumulators.
//   acc[i] = opt_j tile[x0+i+j] + c2*se(j), se(j)=j^2*2^-TL exact dyadic,
//   FFMA-imm form (se compile-time) -> rt 1 on the fma pipe.
// ---------------------------------------------------------------------------
template <int W, int TL, bool ISMAX>
__device__ __forceinline__ void hsweep(const float* __restrict__ base,
                                       float c2, float* __restrict__ acc)
{
    constexpr float SESC = 1.0f / (float)(1 << TL);
#pragma unroll
    for (int u = 0; u < 2 * W + 8; ++u) {
        const float v = base[u + (u >> 3)];
#pragma unroll
        for (int i = 0; i < 8; ++i) {
            const int j = u - W - i;
            if (j >= -W && j <= W) {
                const float jw = (float)(j * j) * SESC;
                const float cand = fmaf(c2, jw, v);
                acc[i] = ISMAX ? fmaxf(acc[i], cand) : fminf(acc[i], cand);
            }
        }
    }
}

// ---------------------------------------------------------------------------
// K1 body: H-dilate one scale. Stage 8 rows (pad W) into skewed smem, sweep.
// ---------------------------------------------------------------------------
template <int W, int TL>
__device__ __forceinline__ void hdil_body(float* __restrict__ s,
                                          const float* __restrict__ sp,
                                          float* __restrict__ dp,
                                          float c2, int t)
{
    constexpr int RW = 256 + 2 * W;
    for (int idx = t; idx < 8 * RW; idx += 256) {
        int rr = idx / RW;
        int pp = idx - rr * RW;
        int xx = pp - W;
        s[rr * SROW + pp + (pp >> 3)] = ((unsigned)xx < 256u) ? sp[rr * 256 + xx]
                                                              : -10000.0f;
    }
    __syncthreads();

    const int r  = t >> 5;
    const int x0 = (t & 31) * 8;
    const float* base = s + r * SROW + x0 + (x0 >> 3);

    float acc[8];
#pragma unroll
    for (int i = 0; i < 8; i++) acc[i] = -3.0e38f;
    hsweep<W, TL, true>(base, c2, acc);

    float* d = dp + r * 256 + x0;
    *(float4*)(d + 0) = make_float4(acc[0], acc[1], acc[2], acc[3]);
    *(float4*)(d + 4) = make_float4(acc[4], acc[5], acc[6], acc[7]);
}

__global__ __launch_bounds__(256, 4) void hdil_all(const float* __restrict__ in,
                                                   float* __restrict__ Apad,
                                                   const float* __restrict__ coefp)
{
    __shared__ float s[8 * SROW];
    const int g = blockIdx.x;          // 0..39: 32 row-groups + 8 pad-fill groups
    const int scale = blockIdx.z;
    const int plane = blockIdx.y;
    const int t = threadIdx.x;
    float* dplane = Apad + (size_t)(scale * NPLANES + plane) * PPL;

    if (g >= 32) {                     // fill this scale's vertical pad rows
        const int pr = (g - 32) * 8;                    // 0..63
        const int prow = (pr < PR) ? pr : (pr + 256);
        const float4 pv = make_float4(-10000.0f, -10000.0f, -10000.0f, -10000.0f);
        for (int idx = t; idx < 8 * 64; idx += 256) {
            int rr = idx >> 6, cc = idx & 63;
            *(float4*)(dplane + (prow + rr) * 256 + cc * 4) = pv;
        }
        return;
    }

    const float c2 = -__ldg(coefp);
    const int rowbase = g * 8;
    const float* sp = in + plane * HW + rowbase * 256;
    float* dp = dplane + (PR + rowbase) * 256;

    if      (scale == 0) hdil_body< 4, 2>(s, sp, dp, c2, t);
    else if (scale == 1) hdil_body< 8, 4>(s, sp, dp, c2, t);
    else if (scale == 2) hdil_body<16, 6>(s, sp, dp, c2, t);
    else                 hdil_body<32, 8>(s, sp, dp, c2, t);
}

// ---------------------------------------------------------------------------
// vsweep: source-centric vertical weighted opt from a padded global plane.
// Thread covers 8 consecutive rows x 2 cols (float2); each row loaded once.
// ---------------------------------------------------------------------------
template <int W, int TL, bool ISMAX>
__device__ __forceinline__ void vsweep(const float* __restrict__ sp, // plane + x
                                       float c2, float2* __restrict__ acc, int y0)
{
    constexpr float SESC = 1.0f / (float)(1 << TL);
#pragma unroll
    for (int u = 0; u < 2 * W + 8; ++u) {
        const float2 v = *(const float2*)(sp + (y0 - W + u) * 256);
#pragma unroll
        for (int i = 0; i < 8; ++i) {
            const int j = u - W - i;
            if (j >= -W && j <= W) {
                const float jw = (float)(j * j) * SESC;
                const float cx = fmaf(c2, jw, v.x);
                const float cy = fmaf(c2, jw, v.y);
                acc[i].x = ISMAX ? fmaxf(acc[i].x, cx) : fminf(acc[i].x, cx);
                acc[i].y = ISMAX ? fmaxf(acc[i].y, cy) : fminf(acc[i].y, cy);
            }
        }
    }
}

// ---------------------------------------------------------------------------
// K2 body: fused V-dilate (padded A -> smem 16-row strip) then H-erode -> C.
// ---------------------------------------------------------------------------
template <int W, int TL>
__device__ __forceinline__ void k2body(const float* __restrict__ Apl,
                                       float* __restrict__ s,
                                       float* __restrict__ Cpl,
                                       float cdil, float cero,
                                       int t, int ytile)
{
    // ---- V-dilate: thread = 2 cols x 8 rows ----
    {
        const int x  = (t & 127) * 2;
        const int y0 = ytile + (t >> 7) * 8;
        float2 acc[8];
#pragma unroll
        for (int i = 0; i < 8; i++) { acc[i].x = -3.0e38f; acc[i].y = -3.0e38f; }
        vsweep<W, TL, true>(Apl + x, cdil, acc, y0);

        // park in skewed smem at p = 32 + x
        const int lr0 = (t >> 7) * 8;
        const int p = 32 + x;
#pragma unroll
        for (int i = 0; i < 8; i++) {
            const int bi = (lr0 + i) * SROW + p + (p >> 3);
            s[bi]     = acc[i].x;
            s[bi + 1] = acc[i].y;
        }
    }

    // x-pads for the 16 rows: cols [0,32) and [288,320) = +1e4 (erosion pad)
    for (int idx = t; idx < 16 * 64; idx += 256) {
        int rr = idx >> 6, cc = idx & 63;
        int p = (cc < 32) ? cc : (cc + 256);
        s[rr * SROW + p + (p >> 3)] = 10000.0f;
    }
    __syncthreads();

    // ---- H-erode from smem: thread = 8 cols x 2 rows ----
    // Staged tile has uniform pad 32; sweep expects pad W -> offset base by 32-W.
    {
        const int r  = t >> 5;
        const int x0 = (t & 31) * 8;
#pragma unroll
        for (int h = 0; h < 2; h++) {
            const int row = h * 8 + r;
            const int b0 = x0 + (32 - W);      // multiple of 4; recompute skew fully
            const float* base = s + row * SROW;

            float acc[8];
#pragma unroll
            for (int i = 0; i < 8; i++) acc[i] = 3.0e38f;
            // inline sweep with full index skew (b0 not 8-aligned for W=4)
            constexpr float SESC = 1.0f / (float)(1 << TL);
#pragma unroll
            for (int u = 0; u < 2 * W + 8; ++u) {
                const int pp = b0 + u;                    // b0 compile-time-ish
                const float v = base[pp + (pp >> 3)];
#pragma unroll
                for (int i = 0; i < 8; ++i) {
                    const int j = u - W - i;
                    if (j >= -W && j <= W) {
                        const float jw = (float)(j * j) * SESC;
                        const float cand = fmaf(cero, jw, v);
                        acc[i] = fminf(acc[i], cand);
                    }
                }
            }

            float* dp = Cpl + (size_t)(ytile + row) * 256 + x0;
            *(float4*)(dp + 0) = make_float4(acc[0], acc[1], acc[2], acc[3]);
            *(float4*)(dp + 4) = make_float4(acc[4], acc[5], acc[6], acc[7]);
        }
    }
}

__global__ __launch_bounds__(256, 4) void vdil_hero_all(const float* __restrict__ Apad,
                                                        float* __restrict__ Cpad,
                                                        const float* __restrict__ coefp)
{
    __shared__ float s[16 * SROW];
    const int scale = blockIdx.z;
    const int plane = blockIdx.y;
    const int gx = blockIdx.x;         // 0..19: 16 strips + 4 pad-fill groups
    const int t = threadIdx.x;
    float* Cpl = Cpad + (size_t)(scale * NPLANES + plane) * PPL;

    if (gx >= 16) {                    // fill C's vertical pad rows (+1e4)
        const int pr = (gx - 16) * 16;
        const int prow = (pr < PR) ? pr : (pr + 256);
        const float4 pv = make_float4(10000.0f, 10000.0f, 10000.0f, 10000.0f);
        for (int idx = t; idx < 16 * 64; idx += 256) {
            int rr = idx >> 6, cc = idx & 63;
            *(float4*)(Cpl + (prow + rr) * 256 + cc * 4) = pv;
        }
        return;
    }

    const float c = __ldg(coefp);
    const float* Apl = Apad + (size_t)(scale * NPLANES + plane) * PPL + PR * 256;
    float* CplD = Cpl + PR * 256;
    const int ytile = gx * 16;

    if      (scale == 0) k2body< 4, 2>(Apl, s, CplD, -c, c, t, ytile);
    else if (scale == 1) k2body< 8, 4>(Apl, s, CplD, -c, c, t, ytile);
    else if (scale == 2) k2body<16, 6>(Apl, s, CplD, -c, c, t, ytile);
    else                 k2body<32, 8>(Apl, s, CplD, -c, c, t, ytile);
}

// ---------------------------------------------------------------------------
// K3: V-erode (padded C -> stacked output), source-centric sweep.
// ---------------------------------------------------------------------------
template <int W, int TL>
__device__ __forceinline__ void vero_body(const float* __restrict__ sp,
                                          float* __restrict__ dp,
                                          float c2, int y0)
{
    float2 acc[8];
#pragma unroll
    for (int i = 0; i < 8; i++) { acc[i].x = 3.0e38f; acc[i].y = 3.0e38f; }
    vsweep<W, TL, false>(sp, c2, acc, y0);
#pragma unroll
    for (int i = 0; i < 8; i++)
        *(float2*)(dp + i * 256) = acc[i];
}

__global__ __launch_bounds__(256, 4) void vero_all(const float* __restrict__ Cpad,
                                                   float* __restrict__ dst,
                                                   const float* __restrict__ coefp)
{
    const int scale = blockIdx.z;
    const int plane = blockIdx.y;
    const int t = threadIdx.x;
    const int x  = (t & 127) * 2;
    const int y0 = blockIdx.x * 16 + (t >> 7) * 8;
    const float c2 = __ldg(coefp);

    const float* sp = Cpad + (size_t)(scale * NPLANES + plane) * PPL + PR * 256 + x;
    float* dp = dst + (size_t)scale * HW + (size_t)plane * 4 * HW + y0 * 256 + x;

    if      (scale == 0) vero_body< 4, 2>(sp, dp, c2, y0);
    else if (scale == 1) vero_body< 8, 4>(sp, dp, c2, y0);
    else if (scale == 2) vero_body<16, 6>(sp, dp, c2, y0);
    else                 vero_body<32, 8>(sp, dp, c2, y0);
}

// ---------------------------------------------------------------------------
// 3 launches: H-dil (in->A) -> fused V-dil+H-ero (A->C) -> V-ero (C->out)
// ---------------------------------------------------------------------------
extern "C" void kernel_launch(void* const* d_in, const int* in_sizes, int n_in,
                              void* d_out, int out_size)
{
    (void)in_sizes; (void)n_in; (void)out_size;
    const float* in   = (const float*)d_in[0];
    const float* coef = (const float*)d_in[1];
    float* out = (float*)d_out;

    float *A = nullptr, *C = nullptr;
    cudaGetSymbolAddress((void**)&A, g_bufA);
    cudaGetSymbolAddress((void**)&C, g_bufC);

    dim3 g1(40, NPLANES, 4);     // 32 row-groups + 8 pad-fill groups
    dim3 g2(20, NPLANES, 4);     // 16 strips + 4 pad-fill groups
    dim3 g3(16, NPLANES, 4);

    hdil_all     <<<g1, 256>>>(in, A, coef);
    vdil_hero_all<<<g2, 256>>>(A, C, coef);
    vero_all     <<<g3, 256>>>(C, out, coef);
}